// round 7
// baseline (speedup 1.0000x reference)
#include <cuda_runtime.h>
#include <cuda_fp16.h>
#include <cuda_bf16.h>
#include <cuda_fp8.h>
#include <cstdint>

// Problem constants
#define IN_F   4096
#define OUT_F  4096
#define RANK   8
#define MTOT   8192
#define KDIM   4096
#define NDIM   4096

// Quantized operand scratch: integer codes in [-8,7] stored as e4m3 (exact)
__device__ uint8_t g_xq[(size_t)MTOT * KDIM];   // 32 MB
__device__ uint8_t g_wq[(size_t)NDIM * KDIM];   // 16 MB

__device__ __forceinline__ float qclipf(float v) {
    return fminf(7.0f, fmaxf(-8.0f, rintf(v)));
}
__device__ __forceinline__ uint32_t pack4_e4m3(float a, float b, float c, float d) {
    uint32_t r0 = __nv_cvt_float_to_fp8(a, __NV_SATFINITE, __NV_E4M3);
    uint32_t r1 = __nv_cvt_float_to_fp8(b, __NV_SATFINITE, __NV_E4M3);
    uint32_t r2 = __nv_cvt_float_to_fp8(c, __NV_SATFINITE, __NV_E4M3);
    uint32_t r3 = __nv_cvt_float_to_fp8(d, __NV_SATFINITE, __NV_E4M3);
    return r0 | (r1 << 8) | (r2 << 16) | (r3 << 24);
}

// ---------------------------------------------------------------------------
// Kernel 1: activation quantization -> packed e4m3 (MLP=4 loads, 16B store)
// ---------------------------------------------------------------------------
__global__ void quant_x_kernel(const float* __restrict__ x,
                               const float* __restrict__ tscales,
                               const int*   __restrict__ step) {
    int t = blockIdx.x * blockDim.x + threadIdx.x;
    const int ngrp = (MTOT * KDIM) / 16;
    if (t >= ngrp) return;
    float inv = 1.0f / tscales[*step];
    const float4* src = reinterpret_cast<const float4*>(x) + (size_t)t * 4;
    float4 v0 = src[0];
    float4 v1 = src[1];
    float4 v2 = src[2];
    float4 v3 = src[3];
    uint4 o;
    o.x = pack4_e4m3(qclipf(v0.x * inv), qclipf(v0.y * inv),
                     qclipf(v0.z * inv), qclipf(v0.w * inv));
    o.y = pack4_e4m3(qclipf(v1.x * inv), qclipf(v1.y * inv),
                     qclipf(v1.z * inv), qclipf(v1.w * inv));
    o.z = pack4_e4m3(qclipf(v2.x * inv), qclipf(v2.y * inv),
                     qclipf(v2.z * inv), qclipf(v2.w * inv));
    o.w = pack4_e4m3(qclipf(v3.x * inv), qclipf(v3.y * inv),
                     qclipf(v3.z * inv), qclipf(v3.w * inv));
    reinterpret_cast<uint4*>(g_xq)[t] = o;
}

// ---------------------------------------------------------------------------
// Kernel 2: LoRA merge + weight quantization -> packed e4m3
// ---------------------------------------------------------------------------
__global__ void quant_w_kernel(const float* __restrict__ W,
                               const float* __restrict__ lA,
                               const float* __restrict__ lB,
                               const float* __restrict__ wscale) {
    int o  = blockIdx.x;
    int i4 = threadIdx.x;
    float b[RANK];
#pragma unroll
    for (int r = 0; r < RANK; r++) b[r] = lB[o * RANK + r];
    float inv = 1.0f / wscale[o];
    float4 w = reinterpret_cast<const float4*>(W + (size_t)o * IN_F)[i4];
    float m0 = w.x, m1 = w.y, m2 = w.z, m3 = w.w;
#pragma unroll
    for (int r = 0; r < RANK; r++) {
        float4 a = reinterpret_cast<const float4*>(lA + (size_t)r * IN_F)[i4];
        m0 += b[r] * a.x; m1 += b[r] * a.y; m2 += b[r] * a.z; m3 += b[r] * a.w;
    }
    reinterpret_cast<uint32_t*>(g_wq)[((size_t)o * IN_F) / 4 + i4] =
        pack4_e4m3(qclipf(m0 * inv), qclipf(m1 * inv),
                   qclipf(m2 * inv), qclipf(m3 * inv));
}

// ---------------------------------------------------------------------------
// Kernel 3: fp8 GEMM with f16-accumulator mma (C=0, exact: |sum|<=2048 int)
// promoted to fp32 master accumulators after every mma.
// CTA tile 128x256x128, 256 threads = 8 warps (2M x 4N), warp tile 64x64.
// 3-stage cp.async, one barrier per K-tile, reg-double-buffered fragments.
// ---------------------------------------------------------------------------
#define BM 128
#define BN 256
#define BK 128
#define KTILES (KDIM / BK)   // 32
#define ASTG (BM * 128)      // 16384
#define BSTG (BN * 128)      // 32768
#define STG  (ASTG + BSTG)   // 49152
#define STAGES 3
#define SMEM_TOTAL (STAGES * STG)   // 147456

__device__ __forceinline__ uint32_t swz128(int row, int chunk) {
    return (uint32_t)(row * 128 + ((chunk ^ (row & 7)) << 4));
}

__device__ __forceinline__ void cp_async16(uint32_t saddr, const void* gaddr) {
    asm volatile("cp.async.cg.shared.global [%0], [%1], 16;\n"
                 :: "r"(saddr), "l"(gaddr));
}

__device__ __forceinline__ void ldm_x4(uint32_t* d, uint32_t addr) {
    asm volatile("ldmatrix.sync.aligned.m8n8.x4.shared.b16 {%0,%1,%2,%3}, [%4];\n"
                 : "=r"(d[0]), "=r"(d[1]), "=r"(d[2]), "=r"(d[3]) : "r"(addr));
}

__global__ __launch_bounds__(256, 1) void gemm_kernel(
    float* __restrict__ out,
    const float* __restrict__ wscale,
    const float* __restrict__ bias,
    const float* __restrict__ tscales,
    const int*  __restrict__ step)
{
    extern __shared__ __align__(128) unsigned char smem[];
    const int tid   = threadIdx.x;
    const int lane  = tid & 31;
    const int warp  = tid >> 5;
    const int warpM = warp >> 2;     // 0..1
    const int warpN = warp & 3;      // 0..3
    const int bm0 = blockIdx.y * BM;
    const int bn0 = blockIdx.x * BN;

    const uint32_t sbase = (uint32_t)__cvta_generic_to_shared(smem);

    float acc[4][8][4];
#pragma unroll
    for (int mi = 0; mi < 4; mi++)
#pragma unroll
        for (int ni = 0; ni < 8; ni++)
#pragma unroll
            for (int c = 0; c < 4; c++) acc[mi][ni][c] = 0.0f;

    auto load_tile = [&](int s, int kt) {
        const int k0 = kt * BK;
        const uint32_t abase = sbase + s * STG;
        const uint32_t bbase = abase + ASTG;
#pragma unroll
        for (int p = 0; p < 4; p++) {
            int ci = tid + p * 256;
            int r = ci >> 3, c = ci & 7;
            cp_async16(abase + swz128(r, c),
                       &g_xq[(size_t)(bm0 + r) * KDIM + k0 + c * 16]);
        }
#pragma unroll
        for (int p = 0; p < 8; p++) {
            int ci = tid + p * 256;
            int r = ci >> 3, c = ci & 7;
            cp_async16(bbase + swz128(r, c),
                       &g_wq[(size_t)(bn0 + r) * KDIM + k0 + c * 16]);
        }
        asm volatile("cp.async.commit_group;\n" ::);
    };

    load_tile(0, 0);
    load_tile(1, 1);

    const int q = lane >> 3;
    const int w = lane & 7;
    const int arow = warpM * 64 + w + 8 * (q & 1);
    const int brow = warpN * 64 + w + 8 * (q & 1);

    uint32_t aF[2][4][4];
    uint32_t bF[2][8][2];

    auto load_frags = [&](uint32_t abase, uint32_t bbase, int kk, int buf) {
        const int ch = 2 * kk + (q >> 1);
#pragma unroll
        for (int mi = 0; mi < 4; mi++)
            ldm_x4(aF[buf][mi], abase + swz128(arow + mi * 16, ch));
#pragma unroll
        for (int j = 0; j < 4; j++) {
            uint32_t t[4];
            ldm_x4(t, bbase + swz128(brow + j * 16, ch));
            bF[buf][2 * j][0] = t[0]; bF[buf][2 * j + 1][0] = t[1];
            bF[buf][2 * j][1] = t[2]; bF[buf][2 * j + 1][1] = t[3];
        }
    };

    // f16-acc mma with C=0; the k32 integer sum (|.|<=2048) is EXACT in f16.
    // Promote to f32 master accumulators right after.
    auto do_mma = [&](int buf) {
#pragma unroll
        for (int mi = 0; mi < 4; mi++)
#pragma unroll
            for (int ni = 0; ni < 8; ni++) {
                uint32_t d0, d1;
                asm volatile(
                    "mma.sync.aligned.m16n8k32.row.col.f16.e4m3.e4m3.f16 "
                    "{%0,%1}, {%2,%3,%4,%5}, {%6,%7}, {%8,%8};\n"
                    : "=r"(d0), "=r"(d1)
                    : "r"(aF[buf][mi][0]), "r"(aF[buf][mi][1]),
                      "r"(aF[buf][mi][2]), "r"(aF[buf][mi][3]),
                      "r"(bF[buf][ni][0]), "r"(bF[buf][ni][1]),
                      "r"(0u));
                float2 f0 = __half22float2(*reinterpret_cast<__half2*>(&d0));
                float2 f1 = __half22float2(*reinterpret_cast<__half2*>(&d1));
                acc[mi][ni][0] += f0.x;
                acc[mi][ni][1] += f0.y;
                acc[mi][ni][2] += f1.x;
                acc[mi][ni][3] += f1.y;
            }
    };

#pragma unroll 1
    for (int kt = 0; kt < KTILES; ++kt) {
        const int s = kt % STAGES;
        if (kt + 2 < KTILES) {
            asm volatile("cp.async.wait_group 1;\n" ::);
        } else {
            asm volatile("cp.async.wait_group 0;\n" ::);
        }
        __syncthreads();
        if (kt + 2 < KTILES) load_tile((kt + 2) % STAGES, kt + 2);

        const uint32_t abase = sbase + s * STG;
        const uint32_t bbase = abase + ASTG;

        load_frags(abase, bbase, 0, 0);
#pragma unroll
        for (int kk = 0; kk < 4; kk++) {
            const int cur = kk & 1;
            if (kk < 3) load_frags(abase, bbase, kk + 1, cur ^ 1);
            do_mma(cur);
        }
    }

    // ------- epilogue: out = acc * ts*scale[o] + bias[o] -------
    const float ts = tscales[*step];
#pragma unroll
    for (int ni = 0; ni < 8; ni++) {
        int gn = bn0 + warpN * 64 + ni * 8 + (lane & 3) * 2;
        float s0 = wscale[gn]     * ts;
        float s1 = wscale[gn + 1] * ts;
        float b0 = bias[gn];
        float b1 = bias[gn + 1];
#pragma unroll
        for (int mi = 0; mi < 4; mi++) {
            int gm = bm0 + warpM * 64 + mi * 16 + (lane >> 2);
            float2 r01;
            r01.x = acc[mi][ni][0] * s0 + b0;
            r01.y = acc[mi][ni][1] * s1 + b1;
            *reinterpret_cast<float2*>(&out[(size_t)gm * NDIM + gn]) = r01;
            float2 r23;
            r23.x = acc[mi][ni][2] * s0 + b0;
            r23.y = acc[mi][ni][3] * s1 + b1;
            *reinterpret_cast<float2*>(&out[(size_t)(gm + 8) * NDIM + gn]) = r23;
        }
    }
}

// ---------------------------------------------------------------------------
// launch: 0=x 1=W 2=lora_A 3=lora_B 4=weight_scale 5=temporal_scales 6=bias 7=step
// ---------------------------------------------------------------------------
extern "C" void kernel_launch(void* const* d_in, const int* in_sizes, int n_in,
                              void* d_out, int out_size) {
    const float* x   = (const float*)d_in[0];
    const float* W   = (const float*)d_in[1];
    const float* lA  = (const float*)d_in[2];
    const float* lB  = (const float*)d_in[3];
    const float* ws  = (const float*)d_in[4];
    const float* tsc = (const float*)d_in[5];
    const float* bia = (const float*)d_in[6];
    const int*   stp = (const int*)  d_in[7];
    float* out = (float*)d_out;

    {
        int ngrp = (MTOT * KDIM) / 16;
        quant_x_kernel<<<(ngrp + 255) / 256, 256>>>(x, tsc, stp);
    }
    quant_w_kernel<<<NDIM, 1024>>>(W, lA, lB, ws);
    {
        static int smem_set = 0;
        if (!smem_set) {
            cudaFuncSetAttribute(gemm_kernel,
                                 cudaFuncAttributeMaxDynamicSharedMemorySize,
                                 SMEM_TOTAL);
            smem_set = 1;
        }
        dim3 grid(NDIM / BN, MTOT / BM);   // (16, 64)
        gemm_kernel<<<grid, 256, SMEM_TOTAL>>>(out, ws, bia, tsc, stp);
    }
}

// round 8
// speedup vs baseline: 1.3001x; 1.3001x over previous
#include <cuda_runtime.h>
#include <cuda_fp16.h>
#include <cuda_bf16.h>
#include <cuda_fp8.h>
#include <cstdint>

// Problem constants
#define IN_F   4096
#define OUT_F  4096
#define RANK   8
#define MTOT   8192
#define KDIM   4096
#define NDIM   4096

// Quantized operand scratch: integer codes in [-8,7] stored as e4m3 (exact)
__device__ uint8_t g_xq[(size_t)MTOT * KDIM];   // 32 MB
__device__ uint8_t g_wq[(size_t)NDIM * KDIM];   // 16 MB

__device__ __forceinline__ float qclipf(float v) {
    return fminf(7.0f, fmaxf(-8.0f, rintf(v)));
}
__device__ __forceinline__ uint32_t pack4_e4m3(float a, float b, float c, float d) {
    uint32_t r0 = __nv_cvt_float_to_fp8(a, __NV_SATFINITE, __NV_E4M3);
    uint32_t r1 = __nv_cvt_float_to_fp8(b, __NV_SATFINITE, __NV_E4M3);
    uint32_t r2 = __nv_cvt_float_to_fp8(c, __NV_SATFINITE, __NV_E4M3);
    uint32_t r3 = __nv_cvt_float_to_fp8(d, __NV_SATFINITE, __NV_E4M3);
    return r0 | (r1 << 8) | (r2 << 16) | (r3 << 24);
}

// ---------------------------------------------------------------------------
// Kernel 1: activation quantization -> packed e4m3 (MLP=4 loads, 16B store)
// ---------------------------------------------------------------------------
__global__ void quant_x_kernel(const float* __restrict__ x,
                               const float* __restrict__ tscales,
                               const int*   __restrict__ step) {
    int t = blockIdx.x * blockDim.x + threadIdx.x;
    const int ngrp = (MTOT * KDIM) / 16;
    if (t >= ngrp) return;
    float inv = 1.0f / tscales[*step];
    const float4* src = reinterpret_cast<const float4*>(x) + (size_t)t * 4;
    float4 v0 = src[0];
    float4 v1 = src[1];
    float4 v2 = src[2];
    float4 v3 = src[3];
    uint4 o;
    o.x = pack4_e4m3(qclipf(v0.x * inv), qclipf(v0.y * inv),
                     qclipf(v0.z * inv), qclipf(v0.w * inv));
    o.y = pack4_e4m3(qclipf(v1.x * inv), qclipf(v1.y * inv),
                     qclipf(v1.z * inv), qclipf(v1.w * inv));
    o.z = pack4_e4m3(qclipf(v2.x * inv), qclipf(v2.y * inv),
                     qclipf(v2.z * inv), qclipf(v2.w * inv));
    o.w = pack4_e4m3(qclipf(v3.x * inv), qclipf(v3.y * inv),
                     qclipf(v3.z * inv), qclipf(v3.w * inv));
    reinterpret_cast<uint4*>(g_xq)[t] = o;
}

// ---------------------------------------------------------------------------
// Kernel 2: LoRA merge + weight quantization -> packed e4m3
// ---------------------------------------------------------------------------
__global__ void quant_w_kernel(const float* __restrict__ W,
                               const float* __restrict__ lA,
                               const float* __restrict__ lB,
                               const float* __restrict__ wscale) {
    int o  = blockIdx.x;
    int i4 = threadIdx.x;
    float b[RANK];
#pragma unroll
    for (int r = 0; r < RANK; r++) b[r] = lB[o * RANK + r];
    float inv = 1.0f / wscale[o];
    float4 w = reinterpret_cast<const float4*>(W + (size_t)o * IN_F)[i4];
    float m0 = w.x, m1 = w.y, m2 = w.z, m3 = w.w;
#pragma unroll
    for (int r = 0; r < RANK; r++) {
        float4 a = reinterpret_cast<const float4*>(lA + (size_t)r * IN_F)[i4];
        m0 += b[r] * a.x; m1 += b[r] * a.y; m2 += b[r] * a.z; m3 += b[r] * a.w;
    }
    reinterpret_cast<uint32_t*>(g_wq)[((size_t)o * IN_F) / 4 + i4] =
        pack4_e4m3(qclipf(m0 * inv), qclipf(m1 * inv),
                   qclipf(m2 * inv), qclipf(m3 * inv));
}

// ---------------------------------------------------------------------------
// Kernel 3: fp8 GEMM, occupancy-heavy variant.
// CTA tile 128x128x128, 256 threads = 8 warps (2M x 4N), warp tile 64x32.
// 3-stage cp.async (32 KB/stage, 96 KB) -> 2 CTAs/SM, 16 warps/SM.
// Single-buffered fragments to stay under 128 regs/thread.
// ---------------------------------------------------------------------------
#define BM 128
#define BN 128
#define BK 128
#define KTILES (KDIM / BK)   // 32
#define ASTG (BM * 128)      // 16384
#define BSTG (BN * 128)      // 16384
#define STG  (ASTG + BSTG)   // 32768
#define STAGES 3
#define SMEM_TOTAL (STAGES * STG)   // 98304

__device__ __forceinline__ uint32_t swz128(int row, int chunk) {
    return (uint32_t)(row * 128 + ((chunk ^ (row & 7)) << 4));
}

__device__ __forceinline__ void cp_async16(uint32_t saddr, const void* gaddr) {
    asm volatile("cp.async.cg.shared.global [%0], [%1], 16;\n"
                 :: "r"(saddr), "l"(gaddr));
}

__device__ __forceinline__ void ldm_x4(uint32_t* d, uint32_t addr) {
    asm volatile("ldmatrix.sync.aligned.m8n8.x4.shared.b16 {%0,%1,%2,%3}, [%4];\n"
                 : "=r"(d[0]), "=r"(d[1]), "=r"(d[2]), "=r"(d[3]) : "r"(addr));
}

__global__ __launch_bounds__(256, 2) void gemm_kernel(
    float* __restrict__ out,
    const float* __restrict__ wscale,
    const float* __restrict__ bias,
    const float* __restrict__ tscales,
    const int*  __restrict__ step)
{
    extern __shared__ __align__(128) unsigned char smem[];
    const int tid   = threadIdx.x;
    const int lane  = tid & 31;
    const int warp  = tid >> 5;
    const int warpM = warp >> 2;     // 0..1
    const int warpN = warp & 3;      // 0..3
    const int bm0 = blockIdx.y * BM;
    const int bn0 = blockIdx.x * BN;

    const uint32_t sbase = (uint32_t)__cvta_generic_to_shared(smem);

    float acc[4][4][4];              // mi(4) x ni(4) x 4 regs  = 64 regs
#pragma unroll
    for (int mi = 0; mi < 4; mi++)
#pragma unroll
        for (int ni = 0; ni < 4; ni++)
#pragma unroll
            for (int c = 0; c < 4; c++) acc[mi][ni][c] = 0.0f;

    // stage loader: A = 1024 chunks (4/thread), B = 1024 chunks (4/thread)
    auto load_tile = [&](int s, int kt) {
        const int k0 = kt * BK;
        const uint32_t abase = sbase + s * STG;
        const uint32_t bbase = abase + ASTG;
#pragma unroll
        for (int p = 0; p < 4; p++) {
            int ci = tid + p * 256;       // 0..1023
            int r = ci >> 3, c = ci & 7;
            cp_async16(abase + swz128(r, c),
                       &g_xq[(size_t)(bm0 + r) * KDIM + k0 + c * 16]);
        }
#pragma unroll
        for (int p = 0; p < 4; p++) {
            int ci = tid + p * 256;
            int r = ci >> 3, c = ci & 7;
            cp_async16(bbase + swz128(r, c),
                       &g_wq[(size_t)(bn0 + r) * KDIM + k0 + c * 16]);
        }
        asm volatile("cp.async.commit_group;\n" ::);
    };

    load_tile(0, 0);
    load_tile(1, 1);

    const int q = lane >> 3;
    const int w = lane & 7;
    const int arow = warpM * 64 + w + 8 * (q & 1);   // + mi*16
    const int brow = warpN * 32 + w + 8 * (q & 1);   // + j*16

#pragma unroll 1
    for (int kt = 0; kt < KTILES; ++kt) {
        const int s = kt % STAGES;
        if (kt + 2 < KTILES) {
            asm volatile("cp.async.wait_group 1;\n" ::);
        } else {
            asm volatile("cp.async.wait_group 0;\n" ::);
        }
        __syncthreads();
        if (kt + 2 < KTILES) load_tile((kt + 2) % STAGES, kt + 2);

        const uint32_t abase = sbase + s * STG;
        const uint32_t bbase = abase + ASTG;

#pragma unroll
        for (int kk = 0; kk < 4; kk++) {
            const int ch = 2 * kk + (q >> 1);
            uint32_t aF[4][4];
            uint32_t bF[4][2];
#pragma unroll
            for (int mi = 0; mi < 4; mi++)
                ldm_x4(aF[mi], abase + swz128(arow + mi * 16, ch));
#pragma unroll
            for (int j = 0; j < 2; j++) {
                uint32_t t[4];
                ldm_x4(t, bbase + swz128(brow + j * 16, ch));
                bF[2 * j][0] = t[0]; bF[2 * j + 1][0] = t[1];
                bF[2 * j][1] = t[2]; bF[2 * j + 1][1] = t[3];
            }
#pragma unroll
            for (int mi = 0; mi < 4; mi++)
#pragma unroll
                for (int ni = 0; ni < 4; ni++) {
                    asm volatile(
                        "mma.sync.aligned.m16n8k32.row.col.f32.e4m3.e4m3.f32 "
                        "{%0,%1,%2,%3}, {%4,%5,%6,%7}, {%8,%9}, {%0,%1,%2,%3};\n"
                        : "+f"(acc[mi][ni][0]), "+f"(acc[mi][ni][1]),
                          "+f"(acc[mi][ni][2]), "+f"(acc[mi][ni][3])
                        : "r"(aF[mi][0]), "r"(aF[mi][1]),
                          "r"(aF[mi][2]), "r"(aF[mi][3]),
                          "r"(bF[ni][0]), "r"(bF[ni][1]));
                }
        }
    }

    // ------- epilogue: out = acc * ts*scale[o] + bias[o] -------
    const float ts = tscales[*step];
#pragma unroll
    for (int ni = 0; ni < 4; ni++) {
        int gn = bn0 + warpN * 32 + ni * 8 + (lane & 3) * 2;
        float s0 = wscale[gn]     * ts;
        float s1 = wscale[gn + 1] * ts;
        float b0 = bias[gn];
        float b1 = bias[gn + 1];
#pragma unroll
        for (int mi = 0; mi < 4; mi++) {
            int gm = bm0 + warpM * 64 + mi * 16 + (lane >> 2);
            float2 r01;
            r01.x = acc[mi][ni][0] * s0 + b0;
            r01.y = acc[mi][ni][1] * s1 + b1;
            *reinterpret_cast<float2*>(&out[(size_t)gm * NDIM + gn]) = r01;
            float2 r23;
            r23.x = acc[mi][ni][2] * s0 + b0;
            r23.y = acc[mi][ni][3] * s1 + b1;
            *reinterpret_cast<float2*>(&out[(size_t)(gm + 8) * NDIM + gn]) = r23;
        }
    }
}

// ---------------------------------------------------------------------------
// launch: 0=x 1=W 2=lora_A 3=lora_B 4=weight_scale 5=temporal_scales 6=bias 7=step
// ---------------------------------------------------------------------------
extern "C" void kernel_launch(void* const* d_in, const int* in_sizes, int n_in,
                              void* d_out, int out_size) {
    const float* x   = (const float*)d_in[0];
    const float* W   = (const float*)d_in[1];
    const float* lA  = (const float*)d_in[2];
    const float* lB  = (const float*)d_in[3];
    const float* ws  = (const float*)d_in[4];
    const float* tsc = (const float*)d_in[5];
    const float* bia = (const float*)d_in[6];
    const int*   stp = (const int*)  d_in[7];
    float* out = (float*)d_out;

    {
        int ngrp = (MTOT * KDIM) / 16;
        quant_x_kernel<<<(ngrp + 255) / 256, 256>>>(x, tsc, stp);
    }
    quant_w_kernel<<<NDIM, 1024>>>(W, lA, lB, ws);
    {
        static int smem_set = 0;
        if (!smem_set) {
            cudaFuncSetAttribute(gemm_kernel,
                                 cudaFuncAttributeMaxDynamicSharedMemorySize,
                                 SMEM_TOTAL);
            smem_set = 1;
        }
        dim3 grid(NDIM / BN, MTOT / BM);   // (32, 64)
        gemm_kernel<<<grid, 256, SMEM_TOTAL>>>(out, ws, bia, tsc, stp);
    }
}

// round 9
// speedup vs baseline: 1.3451x; 1.0346x over previous
#include <cuda_runtime.h>
#include <cuda_fp16.h>
#include <cuda_bf16.h>
#include <cuda_fp8.h>
#include <cstdint>

// Problem constants
#define IN_F   4096
#define OUT_F  4096
#define RANK   8
#define MTOT   8192
#define KDIM   4096
#define NDIM   4096

// Quantized operand scratch: integer codes in [-8,7] stored as e4m3 (exact)
__device__ uint8_t g_xq[(size_t)MTOT * KDIM];   // 32 MB
__device__ uint8_t g_wq[(size_t)NDIM * KDIM];   // 16 MB

__device__ __forceinline__ float qclipf(float v) {
    return fminf(7.0f, fmaxf(-8.0f, rintf(v)));
}
__device__ __forceinline__ uint32_t pack4_e4m3(float a, float b, float c, float d) {
    uint32_t r0 = __nv_cvt_float_to_fp8(a, __NV_SATFINITE, __NV_E4M3);
    uint32_t r1 = __nv_cvt_float_to_fp8(b, __NV_SATFINITE, __NV_E4M3);
    uint32_t r2 = __nv_cvt_float_to_fp8(c, __NV_SATFINITE, __NV_E4M3);
    uint32_t r3 = __nv_cvt_float_to_fp8(d, __NV_SATFINITE, __NV_E4M3);
    return r0 | (r1 << 8) | (r2 << 16) | (r3 << 24);
}

// ---------------------------------------------------------------------------
// Fused quantization kernel.
//   blocks [0, XBLKS)          : activation quant, 8 float4 per thread (MLP=8)
//   blocks [XBLKS, XBLKS+OUT_F): weight LoRA-merge + quant, one block per row
// Both streams run concurrently -> overlapped DRAM traffic.
// ---------------------------------------------------------------------------
#define XGRP   (MTOT * KDIM / 32)      // 32-elem groups: 1,048,576
#define XBLKS  (XGRP / 256)            // 4096 blocks

__global__ __launch_bounds__(256) void quant_fused_kernel(
    const float* __restrict__ x,
    const float* __restrict__ W,
    const float* __restrict__ lA,
    const float* __restrict__ lB,
    const float* __restrict__ wscale,
    const float* __restrict__ tscales,
    const int*   __restrict__ step)
{
    int b = blockIdx.x;
    if (b < XBLKS) {
        // ---- activation quant: one 32-elem group per thread ----
        int t = b * 256 + threadIdx.x;
        float inv = 1.0f / tscales[*step];
        const float4* src = reinterpret_cast<const float4*>(x) + (size_t)t * 8;
        float4 v[8];
#pragma unroll
        for (int i = 0; i < 8; i++) v[i] = src[i];      // front-batched, MLP=8
        uint4 o0, o1;
        o0.x = pack4_e4m3(qclipf(v[0].x * inv), qclipf(v[0].y * inv),
                          qclipf(v[0].z * inv), qclipf(v[0].w * inv));
        o0.y = pack4_e4m3(qclipf(v[1].x * inv), qclipf(v[1].y * inv),
                          qclipf(v[1].z * inv), qclipf(v[1].w * inv));
        o0.z = pack4_e4m3(qclipf(v[2].x * inv), qclipf(v[2].y * inv),
                          qclipf(v[2].z * inv), qclipf(v[2].w * inv));
        o0.w = pack4_e4m3(qclipf(v[3].x * inv), qclipf(v[3].y * inv),
                          qclipf(v[3].z * inv), qclipf(v[3].w * inv));
        o1.x = pack4_e4m3(qclipf(v[4].x * inv), qclipf(v[4].y * inv),
                          qclipf(v[4].z * inv), qclipf(v[4].w * inv));
        o1.y = pack4_e4m3(qclipf(v[5].x * inv), qclipf(v[5].y * inv),
                          qclipf(v[5].z * inv), qclipf(v[5].w * inv));
        o1.z = pack4_e4m3(qclipf(v[6].x * inv), qclipf(v[6].y * inv),
                          qclipf(v[6].z * inv), qclipf(v[6].w * inv));
        o1.w = pack4_e4m3(qclipf(v[7].x * inv), qclipf(v[7].y * inv),
                          qclipf(v[7].z * inv), qclipf(v[7].w * inv));
        reinterpret_cast<uint4*>(g_xq)[2 * t]     = o0;
        reinterpret_cast<uint4*>(g_xq)[2 * t + 1] = o1;
    } else {
        // ---- weight merge + quant: one row per block, 4 float4 per thread ----
        int o = b - XBLKS;
        float br[RANK];
#pragma unroll
        for (int r = 0; r < RANK; r++) br[r] = lB[o * RANK + r];
        float inv = 1.0f / wscale[o];
        const float4* wrow = reinterpret_cast<const float4*>(W + (size_t)o * IN_F);
#pragma unroll
        for (int p = 0; p < 4; p++) {
            int i4 = threadIdx.x + p * 256;      // 0..1023
            float4 w = wrow[i4];
            float m0 = w.x, m1 = w.y, m2 = w.z, m3 = w.w;
#pragma unroll
            for (int r = 0; r < RANK; r++) {
                float4 a = reinterpret_cast<const float4*>(lA + (size_t)r * IN_F)[i4];
                m0 += br[r] * a.x; m1 += br[r] * a.y;
                m2 += br[r] * a.z; m3 += br[r] * a.w;
            }
            reinterpret_cast<uint32_t*>(g_wq)[((size_t)o * IN_F) / 4 + i4] =
                pack4_e4m3(qclipf(m0 * inv), qclipf(m1 * inv),
                           qclipf(m2 * inv), qclipf(m3 * inv));
        }
    }
}

// ---------------------------------------------------------------------------
// fp8 GEMM (round-6 config: proven MAC-bound at the legacy-pipe ceiling).
// CTA tile 128x256x128, 256 threads = 8 warps (2M x 4N), warp tile 64x64.
// 3-stage cp.async, one barrier per K-tile, reg-double-buffered fragments.
// ---------------------------------------------------------------------------
#define BM 128
#define BN 256
#define BK 128
#define KTILES (KDIM / BK)   // 32
#define ASTG (BM * 128)      // 16384
#define BSTG (BN * 128)      // 32768
#define STG  (ASTG + BSTG)   // 49152
#define STAGES 3
#define SMEM_TOTAL (STAGES * STG)   // 147456

__device__ __forceinline__ uint32_t swz128(int row, int chunk) {
    return (uint32_t)(row * 128 + ((chunk ^ (row & 7)) << 4));
}

__device__ __forceinline__ void cp_async16(uint32_t saddr, const void* gaddr) {
    asm volatile("cp.async.cg.shared.global [%0], [%1], 16;\n"
                 :: "r"(saddr), "l"(gaddr));
}

__device__ __forceinline__ void ldm_x4(uint32_t* d, uint32_t addr) {
    asm volatile("ldmatrix.sync.aligned.m8n8.x4.shared.b16 {%0,%1,%2,%3}, [%4];\n"
                 : "=r"(d[0]), "=r"(d[1]), "=r"(d[2]), "=r"(d[3]) : "r"(addr));
}

__global__ __launch_bounds__(256, 1) void gemm_kernel(
    float* __restrict__ out,
    const float* __restrict__ wscale,
    const float* __restrict__ bias,
    const float* __restrict__ tscales,
    const int*  __restrict__ step)
{
    extern __shared__ __align__(128) unsigned char smem[];
    const int tid   = threadIdx.x;
    const int lane  = tid & 31;
    const int warp  = tid >> 5;
    const int warpM = warp >> 2;     // 0..1
    const int warpN = warp & 3;      // 0..3
    const int bm0 = blockIdx.y * BM;
    const int bn0 = blockIdx.x * BN;

    const uint32_t sbase = (uint32_t)__cvta_generic_to_shared(smem);

    float acc[4][8][4];
#pragma unroll
    for (int mi = 0; mi < 4; mi++)
#pragma unroll
        for (int ni = 0; ni < 8; ni++)
#pragma unroll
            for (int c = 0; c < 4; c++) acc[mi][ni][c] = 0.0f;

    auto load_tile = [&](int s, int kt) {
        const int k0 = kt * BK;
        const uint32_t abase = sbase + s * STG;
        const uint32_t bbase = abase + ASTG;
#pragma unroll
        for (int p = 0; p < 4; p++) {
            int ci = tid + p * 256;
            int r = ci >> 3, c = ci & 7;
            cp_async16(abase + swz128(r, c),
                       &g_xq[(size_t)(bm0 + r) * KDIM + k0 + c * 16]);
        }
#pragma unroll
        for (int p = 0; p < 8; p++) {
            int ci = tid + p * 256;
            int r = ci >> 3, c = ci & 7;
            cp_async16(bbase + swz128(r, c),
                       &g_wq[(size_t)(bn0 + r) * KDIM + k0 + c * 16]);
        }
        asm volatile("cp.async.commit_group;\n" ::);
    };

    load_tile(0, 0);
    load_tile(1, 1);

    const int q = lane >> 3;
    const int w = lane & 7;
    const int arow = warpM * 64 + w + 8 * (q & 1);
    const int brow = warpN * 64 + w + 8 * (q & 1);

    uint32_t aF[2][4][4];
    uint32_t bF[2][8][2];

    auto load_frags = [&](uint32_t abase, uint32_t bbase, int kk, int buf) {
        const int ch = 2 * kk + (q >> 1);
#pragma unroll
        for (int mi = 0; mi < 4; mi++)
            ldm_x4(aF[buf][mi], abase + swz128(arow + mi * 16, ch));
#pragma unroll
        for (int j = 0; j < 4; j++) {
            uint32_t t[4];
            ldm_x4(t, bbase + swz128(brow + j * 16, ch));
            bF[buf][2 * j][0] = t[0]; bF[buf][2 * j + 1][0] = t[1];
            bF[buf][2 * j][1] = t[2]; bF[buf][2 * j + 1][1] = t[3];
        }
    };

    auto do_mma = [&](int buf) {
#pragma unroll
        for (int mi = 0; mi < 4; mi++)
#pragma unroll
            for (int ni = 0; ni < 8; ni++) {
                asm volatile(
                    "mma.sync.aligned.m16n8k32.row.col.f32.e4m3.e4m3.f32 "
                    "{%0,%1,%2,%3}, {%4,%5,%6,%7}, {%8,%9}, {%0,%1,%2,%3};\n"
                    : "+f"(acc[mi][ni][0]), "+f"(acc[mi][ni][1]),
                      "+f"(acc[mi][ni][2]), "+f"(acc[mi][ni][3])
                    : "r"(aF[buf][mi][0]), "r"(aF[buf][mi][1]),
                      "r"(aF[buf][mi][2]), "r"(aF[buf][mi][3]),
                      "r"(bF[buf][ni][0]), "r"(bF[buf][ni][1]));
            }
    };

#pragma unroll 1
    for (int kt = 0; kt < KTILES; ++kt) {
        const int s = kt % STAGES;
        if (kt + 2 < KTILES) {
            asm volatile("cp.async.wait_group 1;\n" ::);
        } else {
            asm volatile("cp.async.wait_group 0;\n" ::);
        }
        __syncthreads();
        if (kt + 2 < KTILES) load_tile((kt + 2) % STAGES, kt + 2);

        const uint32_t abase = sbase + s * STG;
        const uint32_t bbase = abase + ASTG;

        load_frags(abase, bbase, 0, 0);
#pragma unroll
        for (int kk = 0; kk < 4; kk++) {
            const int cur = kk & 1;
            if (kk < 3) load_frags(abase, bbase, kk + 1, cur ^ 1);
            do_mma(cur);
        }
    }

    // ------- epilogue: out = acc * ts*scale[o] + bias[o] -------
    const float ts = tscales[*step];
#pragma unroll
    for (int ni = 0; ni < 8; ni++) {
        int gn = bn0 + warpN * 64 + ni * 8 + (lane & 3) * 2;
        float s0 = wscale[gn]     * ts;
        float s1 = wscale[gn + 1] * ts;
        float b0 = bias[gn];
        float b1 = bias[gn + 1];
#pragma unroll
        for (int mi = 0; mi < 4; mi++) {
            int gm = bm0 + warpM * 64 + mi * 16 + (lane >> 2);
            float2 r01;
            r01.x = acc[mi][ni][0] * s0 + b0;
            r01.y = acc[mi][ni][1] * s1 + b1;
            *reinterpret_cast<float2*>(&out[(size_t)gm * NDIM + gn]) = r01;
            float2 r23;
            r23.x = acc[mi][ni][2] * s0 + b0;
            r23.y = acc[mi][ni][3] * s1 + b1;
            *reinterpret_cast<float2*>(&out[(size_t)(gm + 8) * NDIM + gn]) = r23;
        }
    }
}

// ---------------------------------------------------------------------------
// launch: 0=x 1=W 2=lora_A 3=lora_B 4=weight_scale 5=temporal_scales 6=bias 7=step
// ---------------------------------------------------------------------------
extern "C" void kernel_launch(void* const* d_in, const int* in_sizes, int n_in,
                              void* d_out, int out_size) {
    const float* x   = (const float*)d_in[0];
    const float* W   = (const float*)d_in[1];
    const float* lA  = (const float*)d_in[2];
    const float* lB  = (const float*)d_in[3];
    const float* ws  = (const float*)d_in[4];
    const float* tsc = (const float*)d_in[5];
    const float* bia = (const float*)d_in[6];
    const int*   stp = (const int*)  d_in[7];
    float* out = (float*)d_out;

    // fused quant: activation blocks + weight blocks in one grid
    quant_fused_kernel<<<XBLKS + OUT_F, 256>>>(x, W, lA, lB, ws, tsc, stp);

    {
        static int smem_set = 0;
        if (!smem_set) {
            cudaFuncSetAttribute(gemm_kernel,
                                 cudaFuncAttributeMaxDynamicSharedMemorySize,
                                 SMEM_TOTAL);
            smem_set = 1;
        }
        dim3 grid(NDIM / BN, MTOT / BM);   // (16, 64)
        gemm_kernel<<<grid, 256, SMEM_TOTAL>>>(out, ws, bia, tsc, stp);
    }
}